// round 14
// baseline (speedup 1.0000x reference)
#include <cuda_runtime.h>
#include <cuda_bf16.h>
#include <cstdint>

#define HID 128
#define NRAD 6
#define NNODES 100000
#define NNODES_PAD 102400     // 25 chunks of 4096
#define NCHUNK 25
#define E_MAX 2000000
#define LDW4 144              // combined-tile row stride in 32-bit words (576 B)
#define TILE4 (128 * LDW4)    // words per full weight tile
#define MROWS 64              // MLP rows per CTA (2 CTAs/SM)
#define ATILE (MROWS * LDW4)  // words per activation tile

// Static scratch (allocation-free per harness rules)
__device__ float    g_node[(size_t)NNODES * HID];
__device__ int      g_count[NNODES_PAD];
__device__ int      g_start[NNODES + 1];
__device__ int      g_cursor[NNODES];
__device__ int      g_list[E_MAX];
__device__ int      g_bsum[NCHUNK];
__device__ int      g_boff[NCHUNK];
__device__ int      g_idx_is64;
__device__ uint32_t g_wsplit[4][TILE4];   // combined hi/lo fragment-group layout

// ---------------------------------------------------------------------------
// Helpers
// ---------------------------------------------------------------------------
__global__ void detect_idx_kernel(const int* __restrict__ idx32) {
    if (threadIdx.x == 0 && blockIdx.x == 0) {
        int all_zero = 1;
#pragma unroll
        for (int k = 1; k <= 31; k += 2) all_zero &= (idx32[k] == 0);
        g_idx_is64 = all_zero;
    }
}

__device__ __forceinline__ long long load_node(const void* idx, int e, int is64) {
    return is64 ? __ldg(&((const long long*)idx)[e])
                : (long long)__ldg(&((const int*)idx)[e]);
}

__device__ __forceinline__ void split2(float a, float b, uint32_t& hi, uint32_t& lo) {
    __nv_bfloat16 ah = __float2bfloat16(a), bh = __float2bfloat16(b);
    float ar = a - __bfloat162float(ah);
    float br = b - __bfloat162float(bh);
    __nv_bfloat162 h2 = __nv_bfloat162(ah, bh);
    __nv_bfloat162 l2 = __nv_bfloat162(__float2bfloat16(ar), __float2bfloat16(br));
    hi = *reinterpret_cast<uint32_t*>(&h2);
    lo = *reinterpret_cast<uint32_t*>(&l2);
}

// group(s,qc) at word offset 16s+4qc holds {hi_w0, hi_w1, lo_w0, lo_w1},
// w0 = 8s+qc, w1 = w0+4 (w = k-word index 0..63)
__device__ __forceinline__ int frag_pos(int w, int& slot) {
    int s  = w >> 3;
    int rr = w & 7;
    slot = rr >> 2;                 // 0: w0 position, 1: w1 position
    return 16 * s + 4 * (rr & 3);   // group base word
}

// ---------------------------------------------------------------------------
// Weight pre-split into the combined fragment-group layout
// ---------------------------------------------------------------------------
__global__ void prep_weights_kernel(const float* __restrict__ W1,
                                    const float* __restrict__ W2,
                                    const float* __restrict__ W3,
                                    const float* __restrict__ Wout) {
    int q = blockIdx.x * blockDim.x + threadIdx.x;   // 4*128*64 = 32768
    if (q >= 4 * 128 * 64) return;
    int l = q >> 13;
    int rem = q & 8191;
    int n = rem >> 6;
    int w = rem & 63;
    const float* Wl = (l == 0) ? W1 : (l == 1) ? W2 : (l == 2) ? W3 : Wout;
    float2 v = *reinterpret_cast<const float2*>(Wl + n * HID + 2 * w);
    uint32_t hi, lo;
    split2(v.x, v.y, hi, lo);
    int slot;
    int base = n * LDW4 + frag_pos(w, slot);
    g_wsplit[l][base + slot]     = hi;
    g_wsplit[l][base + 2 + slot] = lo;
}

// ---------------------------------------------------------------------------
// Counting-sort pipeline (unchanged — R9/R10 WIN)
// ---------------------------------------------------------------------------
__global__ void zero_count_kernel() {
    int i = blockIdx.x * blockDim.x + threadIdx.x;
    if (i < NNODES_PAD) g_count[i] = 0;
}

__global__ void hist_kernel(const void* __restrict__ idx, int E) {
    int e = blockIdx.x * blockDim.x + threadIdx.x;
    if (e >= E) return;
    long long n = load_node(idx, e, g_idx_is64);
    if ((unsigned long long)n < (unsigned long long)NNODES)
        atomicAdd(&g_count[(int)n], 1);
}

__global__ void scan_bsum_kernel() {
    const int tid  = threadIdx.x;
    const int lane = tid & 31;
    const int warp = tid >> 5;
    __shared__ int s_w[32];

    int i0 = blockIdx.x * 4096 + tid * 4;
    int4 c = *reinterpret_cast<const int4*>(&g_count[i0]);
    int v = c.x + c.y + c.z + c.w;
#pragma unroll
    for (int off = 16; off > 0; off >>= 1)
        v += __shfl_down_sync(0xFFFFFFFFu, v, off);
    if (lane == 0) s_w[warp] = v;
    __syncthreads();
    if (warp == 0) {
        int t = s_w[lane];
#pragma unroll
        for (int off = 16; off > 0; off >>= 1)
            t += __shfl_down_sync(0xFFFFFFFFu, t, off);
        if (lane == 0) g_bsum[blockIdx.x] = t;
    }
}

__global__ void scan_boff_kernel() {
    int lane = threadIdx.x;
    int v = (lane < NCHUNK) ? g_bsum[lane] : 0;
    int incl = v;
#pragma unroll
    for (int off = 1; off < 32; off <<= 1) {
        int t = __shfl_up_sync(0xFFFFFFFFu, incl, off);
        if (lane >= off) incl += t;
    }
    if (lane < NCHUNK) g_boff[lane] = incl - v;
    if (lane == NCHUNK - 1) g_start[NNODES] = incl;
}

__global__ void scan_write_kernel() {
    const int tid  = threadIdx.x;
    const int lane = tid & 31;
    const int warp = tid >> 5;
    __shared__ int s_wsum[32];

    int i0 = blockIdx.x * 4096 + tid * 4;
    int4 c = *reinterpret_cast<const int4*>(&g_count[i0]);
    int s0 = c.x, s1 = s0 + c.y, s2 = s1 + c.z, s3 = s2 + c.w;
    int tsum = s3;

    int incl = tsum;
#pragma unroll
    for (int off = 1; off < 32; off <<= 1) {
        int v = __shfl_up_sync(0xFFFFFFFFu, incl, off);
        if (lane >= off) incl += v;
    }
    if (lane == 31) s_wsum[warp] = incl;
    __syncthreads();
    if (warp == 0) {
        int wi = s_wsum[lane];
#pragma unroll
        for (int off = 1; off < 32; off <<= 1) {
            int t = __shfl_up_sync(0xFFFFFFFFu, wi, off);
            if (lane >= off) wi += t;
        }
        s_wsum[lane] = wi;
    }
    __syncthreads();
    int warp_excl = (warp == 0) ? 0 : s_wsum[warp - 1];
    int tbase = g_boff[blockIdx.x] + warp_excl + (incl - tsum);

    int e0 = tbase, e1 = tbase + s0, e2 = tbase + s1, e3 = tbase + s2;
    if (i0 + 0 < NNODES) { g_start[i0 + 0] = e0; g_cursor[i0 + 0] = e0; }
    if (i0 + 1 < NNODES) { g_start[i0 + 1] = e1; g_cursor[i0 + 1] = e1; }
    if (i0 + 2 < NNODES) { g_start[i0 + 2] = e2; g_cursor[i0 + 2] = e2; }
    if (i0 + 3 < NNODES) { g_start[i0 + 3] = e3; g_cursor[i0 + 3] = e3; }
}

__global__ void fill_kernel(const void* __restrict__ idx, int E) {
    int e = blockIdx.x * blockDim.x + threadIdx.x;
    if (e >= E) return;
    long long n = load_node(idx, e, g_idx_is64);
    if ((unsigned long long)n >= (unsigned long long)NNODES) return;
    int pos = atomicAdd(&g_cursor[(int)n], 1);
    if (pos < E_MAX) g_list[pos] = e;
}

// ---------------------------------------------------------------------------
// Gather: one warp per node (grid-stride), 4-edge unrolled with front-batched
// loads to maximize memory-level parallelism.
// ---------------------------------------------------------------------------
__global__ void gather_kernel(const float* __restrict__ x,
                              const float* __restrict__ rbf,
                              const float* __restrict__ Wrbf) {
    const int lane = threadIdx.x & 31;
    const int gwarp  = (blockIdx.x * blockDim.x + threadIdx.x) >> 5;
    const int nwarps = (gridDim.x * blockDim.x) >> 5;
    const int h0 = lane * 4;

    float w[4][NRAD];
#pragma unroll
    for (int j = 0; j < 4; j++)
#pragma unroll
        for (int r = 0; r < NRAD; r++)
            w[j][r] = __ldg(&Wrbf[(h0 + j) * NRAD + r]);

    for (int n = gwarp; n < NNODES; n += nwarps) {
        const int p0 = __ldg(&g_start[n]);
        const int p1 = __ldg(&g_start[n + 1]);
        float a0 = 0.f, a1 = 0.f, a2 = 0.f, a3 = 0.f;

        int p = p0;
        for (; p + 4 <= p1; p += 4) {
            // batch all independent loads first (4 list, 12 rbf, 4 x-rows)
            int e0 = __ldg(&g_list[p]);
            int e1 = __ldg(&g_list[p + 1]);
            int e2 = __ldg(&g_list[p + 2]);
            int e3 = __ldg(&g_list[p + 3]);
            const float2* q0 = reinterpret_cast<const float2*>(rbf + (size_t)e0 * NRAD);
            const float2* q1 = reinterpret_cast<const float2*>(rbf + (size_t)e1 * NRAD);
            const float2* q2 = reinterpret_cast<const float2*>(rbf + (size_t)e2 * NRAD);
            const float2* q3 = reinterpret_cast<const float2*>(rbf + (size_t)e3 * NRAD);
            float2 ra0 = __ldg(q0 + 0), rb0 = __ldg(q0 + 1), rc0 = __ldg(q0 + 2);
            float2 ra1 = __ldg(q1 + 0), rb1 = __ldg(q1 + 1), rc1 = __ldg(q1 + 2);
            float2 ra2 = __ldg(q2 + 0), rb2 = __ldg(q2 + 1), rc2 = __ldg(q2 + 2);
            float2 ra3 = __ldg(q3 + 0), rb3 = __ldg(q3 + 1), rc3 = __ldg(q3 + 2);
            float4 xv0 = *reinterpret_cast<const float4*>(x + (size_t)e0 * HID + h0);
            float4 xv1 = *reinterpret_cast<const float4*>(x + (size_t)e1 * HID + h0);
            float4 xv2 = *reinterpret_cast<const float4*>(x + (size_t)e2 * HID + h0);
            float4 xv3 = *reinterpret_cast<const float4*>(x + (size_t)e3 * HID + h0);

#define GATE_ACC(ra, rb, rc, xv)                                                          \
            {                                                                             \
                float g0 = w[0][0]*ra.x + w[0][1]*ra.y + w[0][2]*rb.x + w[0][3]*rb.y      \
                         + w[0][4]*rc.x + w[0][5]*rc.y;                                   \
                float g1 = w[1][0]*ra.x + w[1][1]*ra.y + w[1][2]*rb.x + w[1][3]*rb.y      \
                         + w[1][4]*rc.x + w[1][5]*rc.y;                                   \
                float g2 = w[2][0]*ra.x + w[2][1]*ra.y + w[2][2]*rb.x + w[2][3]*rb.y      \
                         + w[2][4]*rc.x + w[2][5]*rc.y;                                   \
                float g3 = w[3][0]*ra.x + w[3][1]*ra.y + w[3][2]*rb.x + w[3][3]*rb.y      \
                         + w[3][4]*rc.x + w[3][5]*rc.y;                                   \
                a0 += g0 * xv.x;  a1 += g1 * xv.y;  a2 += g2 * xv.z;  a3 += g3 * xv.w;    \
            }

            GATE_ACC(ra0, rb0, rc0, xv0)
            GATE_ACC(ra1, rb1, rc1, xv1)
            GATE_ACC(ra2, rb2, rc2, xv2)
            GATE_ACC(ra3, rb3, rc3, xv3)
        }
        for (; p < p1; p++) {
            int e = __ldg(&g_list[p]);
            const float2* q = reinterpret_cast<const float2*>(rbf + (size_t)e * NRAD);
            float2 ra = __ldg(q + 0), rb = __ldg(q + 1), rc = __ldg(q + 2);
            float4 xv = *reinterpret_cast<const float4*>(x + (size_t)e * HID + h0);
            GATE_ACC(ra, rb, rc, xv)
        }
#undef GATE_ACC
        *reinterpret_cast<float4*>(g_node + (size_t)n * HID + h0) =
            make_float4(a0, a1, a2, a3);
    }
}

// ===========================================================================
// Phase 2: fused 4-layer MLP (unchanged — R13 WIN: 64-row CTAs, 2 CTAs/SM)
// ===========================================================================

__device__ __forceinline__ void mma16816(float* acc,
                                         uint32_t a0, uint32_t a1, uint32_t a2, uint32_t a3,
                                         uint32_t b0, uint32_t b1) {
    asm volatile(
        "mma.sync.aligned.m16n8k16.row.col.f32.bf16.bf16.f32 "
        "{%0,%1,%2,%3}, {%4,%5,%6,%7}, {%8,%9}, {%0,%1,%2,%3};"
        : "+f"(acc[0]), "+f"(acc[1]), "+f"(acc[2]), "+f"(acc[3])
        : "r"(a0), "r"(a1), "r"(a2), "r"(a3), "r"(b0), "r"(b1));
}

__global__ void __launch_bounds__(256, 2) mlp_mma_kernel(
    const float* __restrict__ b1, const float* __restrict__ b2,
    const float* __restrict__ b3,
    float* __restrict__ out, int nrows)
{
    extern __shared__ __align__(16) uint32_t sw[];
    uint32_t* s_w = sw;            // combined weight tile [128][LDW4]
    uint32_t* s_a = sw + TILE4;    // combined activation tile [64][LDW4]

    const int tid  = threadIdx.x;
    const int lane = tid & 31;
    const int wid  = tid >> 5;                 // 0..7
    const int qr   = lane >> 2;
    const int qc   = lane & 3;
    const int row0 = blockIdx.x * MROWS;
    const int rloc = (wid & 3) * 16;           // 4 row groups
    const int nh   = wid >> 2;                 // 2 col halves
    const int mAl  = rloc + qr;                // 0..63
    const int mBl  = mAl + 8;
    const int mA   = row0 + mAl;
    const int mB   = row0 + mBl;

    // ---- Stage layer-0 activations into combined fragment groups ----
    for (int q = tid; q < MROWS * 64; q += 256) {
        int r = q >> 6;
        int w = q & 63;
        float2 v = make_float2(0.f, 0.f);
        if (row0 + r < nrows)
            v = *reinterpret_cast<const float2*>(g_node + (size_t)(row0 + r) * HID + 2 * w);
        uint32_t hi, lo;
        split2(v.x, v.y, hi, lo);
        int slot;
        int base = r * LDW4 + frag_pos(w, slot);
        s_a[base + slot]     = hi;
        s_a[base + 2 + slot] = lo;
    }

    const float* Bs[3] = {b1, b2, b3};

    for (int layer = 0; layer < 4; layer++) {
        // ---- Stage weights: straight uint4 copy from pre-split global ----
        {
            const uint4* src = reinterpret_cast<const uint4*>(g_wsplit[layer]);
            uint4* dst = reinterpret_cast<uint4*>(s_w);
            for (int q = tid; q < TILE4 / 4; q += 256)
                dst[q] = src[q];
        }
        __syncthreads();

        float acc[8][4];
#pragma unroll
        for (int t = 0; t < 8; t++)
#pragma unroll
            for (int j = 0; j < 4; j++) acc[t][j] = 0.f;

#pragma unroll
        for (int s = 0; s < 8; s++) {
            int go = 16 * s + 4 * qc;
            uint4 a0 = *reinterpret_cast<const uint4*>(&s_a[mAl * LDW4 + go]);
            uint4 a1 = *reinterpret_cast<const uint4*>(&s_a[mBl * LDW4 + go]);

            // prefetch B for t=0
            int bbase = (nh * 64 + qr) * LDW4 + go;
            uint4 b = *reinterpret_cast<const uint4*>(&s_w[bbase]);

#pragma unroll
            for (int t = 0; t < 8; t++) {
                uint4 cb = b;
                if (t < 7)
                    b = *reinterpret_cast<const uint4*>(&s_w[bbase + (t + 1) * 8 * LDW4]);
                mma16816(acc[t], a0.x, a1.x, a0.y, a1.y, cb.x, cb.y);
                mma16816(acc[t], a0.x, a1.x, a0.y, a1.y, cb.z, cb.w);
                mma16816(acc[t], a0.z, a1.z, a0.w, a1.w, cb.x, cb.y);
            }
        }
        __syncthreads();   // mainloop reads done before epilogue writes s_a / restage s_w

        if (layer < 3) {
            const float* bias = Bs[layer];
#pragma unroll
            for (int t = 0; t < 8; t++) {
                int c0 = nh * 64 + 8 * t + 2 * qc;
                float bb0 = __ldg(&bias[c0]);
                float bb1 = __ldg(&bias[c0 + 1]);
                float v0 = acc[t][0] + bb0;
                float v1 = acc[t][1] + bb1;
                float v2 = acc[t][2] + bb0;
                float v3 = acc[t][3] + bb1;
                v0 = v0 / (1.f + __expf(-v0));
                v1 = v1 / (1.f + __expf(-v1));
                v2 = v2 / (1.f + __expf(-v2));
                v3 = v3 / (1.f + __expf(-v3));
                uint32_t hA, lA, hB, lB;
                split2(v0, v1, hA, lA);
                split2(v2, v3, hB, lB);
                int w = nh * 32 + 4 * t + qc;
                int slot;
                int gp = frag_pos(w, slot);
                s_a[mAl * LDW4 + gp + slot]     = hA;
                s_a[mAl * LDW4 + gp + 2 + slot] = lA;
                s_a[mBl * LDW4 + gp + slot]     = hB;
                s_a[mBl * LDW4 + gp + 2 + slot] = lB;
            }
            // next iteration's post-staging __syncthreads orders these writes
        } else {
#pragma unroll
            for (int t = 0; t < 8; t++) {
                int c0 = nh * 64 + 8 * t + 2 * qc;
                if (mA < nrows)
                    *reinterpret_cast<float2*>(out + (size_t)mA * HID + c0) =
                        make_float2(acc[t][0], acc[t][1]);
                if (mB < nrows)
                    *reinterpret_cast<float2*>(out + (size_t)mB * HID + c0) =
                        make_float2(acc[t][2], acc[t][3]);
            }
        }
    }
}

// ---------------------------------------------------------------------------
// Launch
// ---------------------------------------------------------------------------
extern "C" void kernel_launch(void* const* d_in, const int* in_sizes, int n_in,
                              void* d_out, int out_size) {
    const float* x    = (const float*)d_in[0];
    const float* rbf  = (const float*)d_in[1];
    const void*  idx  = d_in[2];
    const float* Wrbf = (const float*)d_in[3];
    const float* W1   = (const float*)d_in[4];
    const float* b1   = (const float*)d_in[5];
    const float* W2   = (const float*)d_in[6];
    const float* b2   = (const float*)d_in[7];
    const float* W3   = (const float*)d_in[8];
    const float* b3   = (const float*)d_in[9];
    const float* Wout = (const float*)d_in[10];

    const int E     = in_sizes[0] / HID;
    const int nrows = out_size / HID;

    detect_idx_kernel<<<1, 32>>>((const int*)idx);
    prep_weights_kernel<<<(4 * 128 * 64 + 255) / 256, 256>>>(W1, W2, W3, Wout);
    zero_count_kernel<<<(NNODES_PAD + 255) / 256, 256>>>();
    hist_kernel<<<(E + 255) / 256, 256>>>(idx, E);
    scan_bsum_kernel<<<NCHUNK, 1024>>>();
    scan_boff_kernel<<<1, 32>>>();
    scan_write_kernel<<<NCHUNK, 1024>>>();
    fill_kernel<<<(E + 255) / 256, 256>>>(idx, E);
    gather_kernel<<<1184, 256>>>(x, rbf, Wrbf);

    const int smem = (TILE4 + ATILE) * 4;   // 110592 B -> 2 CTAs/SM
    cudaFuncSetAttribute(mlp_mma_kernel, cudaFuncAttributeMaxDynamicSharedMemorySize, smem);
    mlp_mma_kernel<<<(nrows + MROWS - 1) / MROWS, 256, smem>>>(
        b1, b2, b3, (float*)d_out, nrows);
}

// round 15
// speedup vs baseline: 1.1485x; 1.1485x over previous
#include <cuda_runtime.h>
#include <cuda_bf16.h>
#include <cstdint>

#define HID 128
#define NRAD 6
#define NNODES 100000
#define NNODES_PAD 102400     // 25 chunks of 4096
#define NCHUNK 25
#define E_MAX 2000000
#define LDW4 144              // combined-tile row stride in 32-bit words (576 B)
#define TILE4 (128 * LDW4)    // words per full weight tile
#define MROWS 64              // MLP rows per CTA (2 CTAs/SM)
#define ATILE (MROWS * LDW4)  // words per activation tile

// Static scratch (allocation-free per harness rules)
__device__ float    g_node[(size_t)NNODES * HID];
__device__ int      g_count[NNODES_PAD];
__device__ int      g_start[NNODES + 1];
__device__ int      g_cursor[NNODES];
__device__ int      g_list[E_MAX];
__device__ int      g_bsum[NCHUNK];
__device__ int      g_boff[NCHUNK];
__device__ int      g_idx_is64;
__device__ uint32_t g_wsplit[4][TILE4];   // combined hi/lo fragment-group layout

// ---------------------------------------------------------------------------
// Helpers
// ---------------------------------------------------------------------------
__global__ void detect_idx_kernel(const int* __restrict__ idx32) {
    if (threadIdx.x == 0 && blockIdx.x == 0) {
        int all_zero = 1;
#pragma unroll
        for (int k = 1; k <= 31; k += 2) all_zero &= (idx32[k] == 0);
        g_idx_is64 = all_zero;
    }
}

__device__ __forceinline__ long long load_node(const void* idx, int e, int is64) {
    return is64 ? __ldg(&((const long long*)idx)[e])
                : (long long)__ldg(&((const int*)idx)[e]);
}

__device__ __forceinline__ void split2(float a, float b, uint32_t& hi, uint32_t& lo) {
    __nv_bfloat16 ah = __float2bfloat16(a), bh = __float2bfloat16(b);
    float ar = a - __bfloat162float(ah);
    float br = b - __bfloat162float(bh);
    __nv_bfloat162 h2 = __nv_bfloat162(ah, bh);
    __nv_bfloat162 l2 = __nv_bfloat162(__float2bfloat16(ar), __float2bfloat16(br));
    hi = *reinterpret_cast<uint32_t*>(&h2);
    lo = *reinterpret_cast<uint32_t*>(&l2);
}

// group(s,qc) at word offset 16s+4qc holds {hi_w0, hi_w1, lo_w0, lo_w1},
// w0 = 8s+qc, w1 = w0+4 (w = k-word index 0..63)
__device__ __forceinline__ int frag_pos(int w, int& slot) {
    int s  = w >> 3;
    int rr = w & 7;
    slot = rr >> 2;                 // 0: w0 position, 1: w1 position
    return 16 * s + 4 * (rr & 3);   // group base word
}

// ---------------------------------------------------------------------------
// Weight pre-split into the combined fragment-group layout
// ---------------------------------------------------------------------------
__global__ void prep_weights_kernel(const float* __restrict__ W1,
                                    const float* __restrict__ W2,
                                    const float* __restrict__ W3,
                                    const float* __restrict__ Wout) {
    int q = blockIdx.x * blockDim.x + threadIdx.x;   // 4*128*64 = 32768
    if (q >= 4 * 128 * 64) return;
    int l = q >> 13;
    int rem = q & 8191;
    int n = rem >> 6;
    int w = rem & 63;
    const float* Wl = (l == 0) ? W1 : (l == 1) ? W2 : (l == 2) ? W3 : Wout;
    float2 v = *reinterpret_cast<const float2*>(Wl + n * HID + 2 * w);
    uint32_t hi, lo;
    split2(v.x, v.y, hi, lo);
    int slot;
    int base = n * LDW4 + frag_pos(w, slot);
    g_wsplit[l][base + slot]     = hi;
    g_wsplit[l][base + 2 + slot] = lo;
}

// ---------------------------------------------------------------------------
// Counting-sort pipeline (unchanged — R9/R10 WIN)
// ---------------------------------------------------------------------------
__global__ void zero_count_kernel() {
    int i = blockIdx.x * blockDim.x + threadIdx.x;
    if (i < NNODES_PAD) g_count[i] = 0;
}

__global__ void hist_kernel(const void* __restrict__ idx, int E) {
    int e = blockIdx.x * blockDim.x + threadIdx.x;
    if (e >= E) return;
    long long n = load_node(idx, e, g_idx_is64);
    if ((unsigned long long)n < (unsigned long long)NNODES)
        atomicAdd(&g_count[(int)n], 1);
}

__global__ void scan_bsum_kernel() {
    const int tid  = threadIdx.x;
    const int lane = tid & 31;
    const int warp = tid >> 5;
    __shared__ int s_w[32];

    int i0 = blockIdx.x * 4096 + tid * 4;
    int4 c = *reinterpret_cast<const int4*>(&g_count[i0]);
    int v = c.x + c.y + c.z + c.w;
#pragma unroll
    for (int off = 16; off > 0; off >>= 1)
        v += __shfl_down_sync(0xFFFFFFFFu, v, off);
    if (lane == 0) s_w[warp] = v;
    __syncthreads();
    if (warp == 0) {
        int t = s_w[lane];
#pragma unroll
        for (int off = 16; off > 0; off >>= 1)
            t += __shfl_down_sync(0xFFFFFFFFu, t, off);
        if (lane == 0) g_bsum[blockIdx.x] = t;
    }
}

__global__ void scan_boff_kernel() {
    int lane = threadIdx.x;
    int v = (lane < NCHUNK) ? g_bsum[lane] : 0;
    int incl = v;
#pragma unroll
    for (int off = 1; off < 32; off <<= 1) {
        int t = __shfl_up_sync(0xFFFFFFFFu, incl, off);
        if (lane >= off) incl += t;
    }
    if (lane < NCHUNK) g_boff[lane] = incl - v;
    if (lane == NCHUNK - 1) g_start[NNODES] = incl;
}

__global__ void scan_write_kernel() {
    const int tid  = threadIdx.x;
    const int lane = tid & 31;
    const int warp = tid >> 5;
    __shared__ int s_wsum[32];

    int i0 = blockIdx.x * 4096 + tid * 4;
    int4 c = *reinterpret_cast<const int4*>(&g_count[i0]);
    int s0 = c.x, s1 = s0 + c.y, s2 = s1 + c.z, s3 = s2 + c.w;
    int tsum = s3;

    int incl = tsum;
#pragma unroll
    for (int off = 1; off < 32; off <<= 1) {
        int v = __shfl_up_sync(0xFFFFFFFFu, incl, off);
        if (lane >= off) incl += v;
    }
    if (lane == 31) s_wsum[warp] = incl;
    __syncthreads();
    if (warp == 0) {
        int wi = s_wsum[lane];
#pragma unroll
        for (int off = 1; off < 32; off <<= 1) {
            int t = __shfl_up_sync(0xFFFFFFFFu, wi, off);
            if (lane >= off) wi += t;
        }
        s_wsum[lane] = wi;
    }
    __syncthreads();
    int warp_excl = (warp == 0) ? 0 : s_wsum[warp - 1];
    int tbase = g_boff[blockIdx.x] + warp_excl + (incl - tsum);

    int e0 = tbase, e1 = tbase + s0, e2 = tbase + s1, e3 = tbase + s2;
    if (i0 + 0 < NNODES) { g_start[i0 + 0] = e0; g_cursor[i0 + 0] = e0; }
    if (i0 + 1 < NNODES) { g_start[i0 + 1] = e1; g_cursor[i0 + 1] = e1; }
    if (i0 + 2 < NNODES) { g_start[i0 + 2] = e2; g_cursor[i0 + 2] = e2; }
    if (i0 + 3 < NNODES) { g_start[i0 + 3] = e3; g_cursor[i0 + 3] = e3; }
}

__global__ void fill_kernel(const void* __restrict__ idx, int E) {
    int e = blockIdx.x * blockDim.x + threadIdx.x;
    if (e >= E) return;
    long long n = load_node(idx, e, g_idx_is64);
    if ((unsigned long long)n >= (unsigned long long)NNODES) return;
    int pos = atomicAdd(&g_cursor[(int)n], 1);
    if (pos < E_MAX) g_list[pos] = e;
}

// ---------------------------------------------------------------------------
// Gather: one warp per node (grid-stride), 2-edge unrolled (R13 WIN state —
// wider front-batching measured WORSE via L1tex-queue spread; do not touch)
// ---------------------------------------------------------------------------
__global__ void gather_kernel(const float* __restrict__ x,
                              const float* __restrict__ rbf,
                              const float* __restrict__ Wrbf) {
    const int lane = threadIdx.x & 31;
    const int gwarp  = (blockIdx.x * blockDim.x + threadIdx.x) >> 5;
    const int nwarps = (gridDim.x * blockDim.x) >> 5;
    const int h0 = lane * 4;

    float w[4][NRAD];
#pragma unroll
    for (int j = 0; j < 4; j++)
#pragma unroll
        for (int r = 0; r < NRAD; r++)
            w[j][r] = __ldg(&Wrbf[(h0 + j) * NRAD + r]);

    for (int n = gwarp; n < NNODES; n += nwarps) {
        const int p0 = __ldg(&g_start[n]);
        const int p1 = __ldg(&g_start[n + 1]);
        float a0 = 0.f, a1 = 0.f, a2 = 0.f, a3 = 0.f;

        int p = p0;
        for (; p + 2 <= p1; p += 2) {
            int e0 = __ldg(&g_list[p]);
            int e1 = __ldg(&g_list[p + 1]);
            const float2* q0 = reinterpret_cast<const float2*>(rbf + (size_t)e0 * NRAD);
            const float2* q1 = reinterpret_cast<const float2*>(rbf + (size_t)e1 * NRAD);
            float2 ra0 = __ldg(q0 + 0), rb0 = __ldg(q0 + 1), rc0 = __ldg(q0 + 2);
            float2 ra1 = __ldg(q1 + 0), rb1 = __ldg(q1 + 1), rc1 = __ldg(q1 + 2);
            float4 xv0 = *reinterpret_cast<const float4*>(x + (size_t)e0 * HID + h0);
            float4 xv1 = *reinterpret_cast<const float4*>(x + (size_t)e1 * HID + h0);

            float g00 = w[0][0]*ra0.x + w[0][1]*ra0.y + w[0][2]*rb0.x + w[0][3]*rb0.y + w[0][4]*rc0.x + w[0][5]*rc0.y;
            float g01 = w[1][0]*ra0.x + w[1][1]*ra0.y + w[1][2]*rb0.x + w[1][3]*rb0.y + w[1][4]*rc0.x + w[1][5]*rc0.y;
            float g02 = w[2][0]*ra0.x + w[2][1]*ra0.y + w[2][2]*rb0.x + w[2][3]*rb0.y + w[2][4]*rc0.x + w[2][5]*rc0.y;
            float g03 = w[3][0]*ra0.x + w[3][1]*ra0.y + w[3][2]*rb0.x + w[3][3]*rb0.y + w[3][4]*rc0.x + w[3][5]*rc0.y;
            a0 += g00 * xv0.x;  a1 += g01 * xv0.y;  a2 += g02 * xv0.z;  a3 += g03 * xv0.w;

            float g10 = w[0][0]*ra1.x + w[0][1]*ra1.y + w[0][2]*rb1.x + w[0][3]*rb1.y + w[0][4]*rc1.x + w[0][5]*rc1.y;
            float g11 = w[1][0]*ra1.x + w[1][1]*ra1.y + w[1][2]*rb1.x + w[1][3]*rb1.y + w[1][4]*rc1.x + w[1][5]*rc1.y;
            float g12 = w[2][0]*ra1.x + w[2][1]*ra1.y + w[2][2]*rb1.x + w[2][3]*rb1.y + w[2][4]*rc1.x + w[2][5]*rc1.y;
            float g13 = w[3][0]*ra1.x + w[3][1]*ra1.y + w[3][2]*rb1.x + w[3][3]*rb1.y + w[3][4]*rc1.x + w[3][5]*rc1.y;
            a0 += g10 * xv1.x;  a1 += g11 * xv1.y;  a2 += g12 * xv1.z;  a3 += g13 * xv1.w;
        }
        if (p < p1) {
            int e = __ldg(&g_list[p]);
            const float2* q = reinterpret_cast<const float2*>(rbf + (size_t)e * NRAD);
            float2 ra = __ldg(q + 0), rb = __ldg(q + 1), rc = __ldg(q + 2);
            float4 xv = *reinterpret_cast<const float4*>(x + (size_t)e * HID + h0);
            float g0 = w[0][0]*ra.x + w[0][1]*ra.y + w[0][2]*rb.x + w[0][3]*rb.y + w[0][4]*rc.x + w[0][5]*rc.y;
            float g1 = w[1][0]*ra.x + w[1][1]*ra.y + w[1][2]*rb.x + w[1][3]*rb.y + w[1][4]*rc.x + w[1][5]*rc.y;
            float g2 = w[2][0]*ra.x + w[2][1]*ra.y + w[2][2]*rb.x + w[2][3]*rb.y + w[2][4]*rc.x + w[2][5]*rc.y;
            float g3 = w[3][0]*ra.x + w[3][1]*ra.y + w[3][2]*rb.x + w[3][3]*rb.y + w[3][4]*rc.x + w[3][5]*rc.y;
            a0 += g0 * xv.x;  a1 += g1 * xv.y;  a2 += g2 * xv.z;  a3 += g3 * xv.w;
        }
        *reinterpret_cast<float4*>(g_node + (size_t)n * HID + h0) =
            make_float4(a0, a1, a2, a3);
    }
}

// ===========================================================================
// Phase 2: fused 4-layer MLP (R13 WIN structure: 64-row CTAs, 2 CTAs/SM).
// Only change vs R13: weight staging via cp.async.cg (same barrier position).
// ===========================================================================

__device__ __forceinline__ void mma16816(float* acc,
                                         uint32_t a0, uint32_t a1, uint32_t a2, uint32_t a3,
                                         uint32_t b0, uint32_t b1) {
    asm volatile(
        "mma.sync.aligned.m16n8k16.row.col.f32.bf16.bf16.f32 "
        "{%0,%1,%2,%3}, {%4,%5,%6,%7}, {%8,%9}, {%0,%1,%2,%3};"
        : "+f"(acc[0]), "+f"(acc[1]), "+f"(acc[2]), "+f"(acc[3])
        : "r"(a0), "r"(a1), "r"(a2), "r"(a3), "r"(b0), "r"(b1));
}

__device__ __forceinline__ void cp16(uint32_t smem_addr, const void* gptr) {
    asm volatile("cp.async.cg.shared.global [%0], [%1], 16;"
                 :: "r"(smem_addr), "l"(gptr) : "memory");
}

__global__ void __launch_bounds__(256, 2) mlp_mma_kernel(
    const float* __restrict__ b1, const float* __restrict__ b2,
    const float* __restrict__ b3,
    float* __restrict__ out, int nrows)
{
    extern __shared__ __align__(16) uint32_t sw[];
    uint32_t* s_w = sw;            // combined weight tile [128][LDW4]
    uint32_t* s_a = sw + TILE4;    // combined activation tile [64][LDW4]

    const int tid  = threadIdx.x;
    const int lane = tid & 31;
    const int wid  = tid >> 5;                 // 0..7
    const int qr   = lane >> 2;
    const int qc   = lane & 3;
    const int row0 = blockIdx.x * MROWS;
    const int rloc = (wid & 3) * 16;           // 4 row groups
    const int nh   = wid >> 2;                 // 2 col halves
    const int mAl  = rloc + qr;                // 0..63
    const int mBl  = mAl + 8;
    const int mA   = row0 + mAl;
    const int mB   = row0 + mBl;

    const uint32_t s_w_u32 = (uint32_t)__cvta_generic_to_shared(s_w);

    // ---- Stage layer-0 activations into combined fragment groups ----
    for (int q = tid; q < MROWS * 64; q += 256) {
        int r = q >> 6;
        int w = q & 63;
        float2 v = make_float2(0.f, 0.f);
        if (row0 + r < nrows)
            v = *reinterpret_cast<const float2*>(g_node + (size_t)(row0 + r) * HID + 2 * w);
        uint32_t hi, lo;
        split2(v.x, v.y, hi, lo);
        int slot;
        int base = r * LDW4 + frag_pos(w, slot);
        s_a[base + slot]     = hi;
        s_a[base + 2 + slot] = lo;
    }

    const float* Bs[3] = {b1, b2, b3};

    for (int layer = 0; layer < 4; layer++) {
        // ---- Stage weights via cp.async (completes at the same point the
        //      old uint4 copy did: before this layer's __syncthreads) ----
        {
            const uint4* src = reinterpret_cast<const uint4*>(g_wsplit[layer]);
            for (int q = tid; q < TILE4 / 4; q += 256)
                cp16(s_w_u32 + q * 16, src + q);
            asm volatile("cp.async.commit_group;" ::: "memory");
            asm volatile("cp.async.wait_group 0;" ::: "memory");
        }
        __syncthreads();

        float acc[8][4];
#pragma unroll
        for (int t = 0; t < 8; t++)
#pragma unroll
            for (int j = 0; j < 4; j++) acc[t][j] = 0.f;

#pragma unroll
        for (int s = 0; s < 8; s++) {
            int go = 16 * s + 4 * qc;
            uint4 a0 = *reinterpret_cast<const uint4*>(&s_a[mAl * LDW4 + go]);
            uint4 a1 = *reinterpret_cast<const uint4*>(&s_a[mBl * LDW4 + go]);

            // prefetch B for t=0
            int bbase = (nh * 64 + qr) * LDW4 + go;
            uint4 b = *reinterpret_cast<const uint4*>(&s_w[bbase]);

#pragma unroll
            for (int t = 0; t < 8; t++) {
                uint4 cb = b;
                if (t < 7)
                    b = *reinterpret_cast<const uint4*>(&s_w[bbase + (t + 1) * 8 * LDW4]);
                mma16816(acc[t], a0.x, a1.x, a0.y, a1.y, cb.x, cb.y);
                mma16816(acc[t], a0.x, a1.x, a0.y, a1.y, cb.z, cb.w);
                mma16816(acc[t], a0.z, a1.z, a0.w, a1.w, cb.x, cb.y);
            }
        }
        __syncthreads();   // mainloop reads done before epilogue writes s_a / restage s_w

        if (layer < 3) {
            const float* bias = Bs[layer];
#pragma unroll
            for (int t = 0; t < 8; t++) {
                int c0 = nh * 64 + 8 * t + 2 * qc;
                float bb0 = __ldg(&bias[c0]);
                float bb1 = __ldg(&bias[c0 + 1]);
                float v0 = acc[t][0] + bb0;
                float v1 = acc[t][1] + bb1;
                float v2 = acc[t][2] + bb0;
                float v3 = acc[t][3] + bb1;
                v0 = v0 / (1.f + __expf(-v0));
                v1 = v1 / (1.f + __expf(-v1));
                v2 = v2 / (1.f + __expf(-v2));
                v3 = v3 / (1.f + __expf(-v3));
                uint32_t hA, lA, hB, lB;
                split2(v0, v1, hA, lA);
                split2(v2, v3, hB, lB);
                int w = nh * 32 + 4 * t + qc;
                int slot;
                int gp = frag_pos(w, slot);
                s_a[mAl * LDW4 + gp + slot]     = hA;
                s_a[mAl * LDW4 + gp + 2 + slot] = lA;
                s_a[mBl * LDW4 + gp + slot]     = hB;
                s_a[mBl * LDW4 + gp + 2 + slot] = lB;
            }
            // next iteration's post-staging __syncthreads orders these writes
        } else {
#pragma unroll
            for (int t = 0; t < 8; t++) {
                int c0 = nh * 64 + 8 * t + 2 * qc;
                if (mA < nrows)
                    *reinterpret_cast<float2*>(out + (size_t)mA * HID + c0) =
                        make_float2(acc[t][0], acc[t][1]);
                if (mB < nrows)
                    *reinterpret_cast<float2*>(out + (size_t)mB * HID + c0) =
                        make_float2(acc[t][2], acc[t][3]);
            }
        }
    }
}

// ---------------------------------------------------------------------------
// Launch
// ---------------------------------------------------------------------------
extern "C" void kernel_launch(void* const* d_in, const int* in_sizes, int n_in,
                              void* d_out, int out_size) {
    const float* x    = (const float*)d_in[0];
    const float* rbf  = (const float*)d_in[1];
    const void*  idx  = d_in[2];
    const float* Wrbf = (const float*)d_in[3];
    const float* W1   = (const float*)d_in[4];
    const float* b1   = (const float*)d_in[5];
    const float* W2   = (const float*)d_in[6];
    const float* b2   = (const float*)d_in[7];
    const float* W3   = (const float*)d_in[8];
    const float* b3   = (const float*)d_in[9];
    const float* Wout = (const float*)d_in[10];

    const int E     = in_sizes[0] / HID;
    const int nrows = out_size / HID;

    detect_idx_kernel<<<1, 32>>>((const int*)idx);
    prep_weights_kernel<<<(4 * 128 * 64 + 255) / 256, 256>>>(W1, W2, W3, Wout);
    zero_count_kernel<<<(NNODES_PAD + 255) / 256, 256>>>();
    hist_kernel<<<(E + 255) / 256, 256>>>(idx, E);
    scan_bsum_kernel<<<NCHUNK, 1024>>>();
    scan_boff_kernel<<<1, 32>>>();
    scan_write_kernel<<<NCHUNK, 1024>>>();
    fill_kernel<<<(E + 255) / 256, 256>>>(idx, E);
    gather_kernel<<<1184, 256>>>(x, rbf, Wrbf);

    const int smem = (TILE4 + ATILE) * 4;   // 110592 B -> 2 CTAs/SM
    cudaFuncSetAttribute(mlp_mma_kernel, cudaFuncAttributeMaxDynamicSharedMemorySize, smem);
    mlp_mma_kernel<<<(nrows + MROWS - 1) / MROWS, 256, smem>>>(
        b1, b2, b3, (float*)d_out, nrows);
}

// round 17
// speedup vs baseline: 1.1498x; 1.0011x over previous
#include <cuda_runtime.h>
#include <cuda_bf16.h>
#include <cstdint>

#define HID 128
#define NRAD 6
#define NNODES 100000
#define NNODES_PAD 102400     // 25 chunks of 4096
#define NCHUNK 25
#define E_MAX 2000000
#define LDW4 144              // combined-tile row stride in 32-bit words (576 B)
#define TILE4 (128 * LDW4)    // words per full weight tile
#define MROWS 64              // MLP rows per CTA (2 CTAs/SM)
#define ATILE (MROWS * LDW4)  // words per activation tile

// Static scratch (allocation-free per harness rules)
__device__ float    g_node[(size_t)NNODES * HID];
__device__ int      g_count[NNODES_PAD];
__device__ int      g_start[NNODES + 1];
__device__ int      g_cursor[NNODES];
__device__ int      g_list[E_MAX];
__device__ int      g_bsum[NCHUNK];
__device__ int      g_boff[NCHUNK];
__device__ int      g_idx_is64;
__device__ uint32_t g_wsplit[4][TILE4];   // combined hi/lo fragment-group layout

// ---------------------------------------------------------------------------
// Helpers
// ---------------------------------------------------------------------------
__global__ void detect_idx_kernel(const int* __restrict__ idx32) {
    if (threadIdx.x == 0 && blockIdx.x == 0) {
        int all_zero = 1;
#pragma unroll
        for (int k = 1; k <= 31; k += 2) all_zero &= (idx32[k] == 0);
        g_idx_is64 = all_zero;
    }
}

__device__ __forceinline__ long long load_node(const void* idx, int e, int is64) {
    return is64 ? __ldg(&((const long long*)idx)[e])
                : (long long)__ldg(&((const int*)idx)[e]);
}

__device__ __forceinline__ void split2(float a, float b, uint32_t& hi, uint32_t& lo) {
    __nv_bfloat16 ah = __float2bfloat16(a), bh = __float2bfloat16(b);
    float ar = a - __bfloat162float(ah);
    float br = b - __bfloat162float(bh);
    __nv_bfloat162 h2 = __nv_bfloat162(ah, bh);
    __nv_bfloat162 l2 = __nv_bfloat162(__float2bfloat16(ar), __float2bfloat16(br));
    hi = *reinterpret_cast<uint32_t*>(&h2);
    lo = *reinterpret_cast<uint32_t*>(&l2);
}

// group(s,qc) at word offset 16s+4qc holds {hi_w0, hi_w1, lo_w0, lo_w1},
// w0 = 8s+qc, w1 = w0+4 (w = k-word index 0..63)
__device__ __forceinline__ int frag_pos(int w, int& slot) {
    int s  = w >> 3;
    int rr = w & 7;
    slot = rr >> 2;                 // 0: w0 position, 1: w1 position
    return 16 * s + 4 * (rr & 3);   // group base word
}

// ---------------------------------------------------------------------------
// Weight pre-split into the combined fragment-group layout
// ---------------------------------------------------------------------------
__global__ void prep_weights_kernel(const float* __restrict__ W1,
                                    const float* __restrict__ W2,
                                    const float* __restrict__ W3,
                                    const float* __restrict__ Wout) {
    int q = blockIdx.x * blockDim.x + threadIdx.x;   // 4*128*64 = 32768
    if (q >= 4 * 128 * 64) return;
    int l = q >> 13;
    int rem = q & 8191;
    int n = rem >> 6;
    int w = rem & 63;
    const float* Wl = (l == 0) ? W1 : (l == 1) ? W2 : (l == 2) ? W3 : Wout;
    float2 v = *reinterpret_cast<const float2*>(Wl + n * HID + 2 * w);
    uint32_t hi, lo;
    split2(v.x, v.y, hi, lo);
    int slot;
    int base = n * LDW4 + frag_pos(w, slot);
    g_wsplit[l][base + slot]     = hi;
    g_wsplit[l][base + 2 + slot] = lo;
}

// ---------------------------------------------------------------------------
// Counting-sort pipeline (unchanged — R9/R10 WIN)
// ---------------------------------------------------------------------------
__global__ void zero_count_kernel() {
    int i = blockIdx.x * blockDim.x + threadIdx.x;
    if (i < NNODES_PAD) g_count[i] = 0;
}

__global__ void hist_kernel(const void* __restrict__ idx, int E) {
    int e = blockIdx.x * blockDim.x + threadIdx.x;
    if (e >= E) return;
    long long n = load_node(idx, e, g_idx_is64);
    if ((unsigned long long)n < (unsigned long long)NNODES)
        atomicAdd(&g_count[(int)n], 1);
}

__global__ void scan_bsum_kernel() {
    const int tid  = threadIdx.x;
    const int lane = tid & 31;
    const int warp = tid >> 5;
    __shared__ int s_w[32];

    int i0 = blockIdx.x * 4096 + tid * 4;
    int4 c = *reinterpret_cast<const int4*>(&g_count[i0]);
    int v = c.x + c.y + c.z + c.w;
#pragma unroll
    for (int off = 16; off > 0; off >>= 1)
        v += __shfl_down_sync(0xFFFFFFFFu, v, off);
    if (lane == 0) s_w[warp] = v;
    __syncthreads();
    if (warp == 0) {
        int t = s_w[lane];
#pragma unroll
        for (int off = 16; off > 0; off >>= 1)
            t += __shfl_down_sync(0xFFFFFFFFu, t, off);
        if (lane == 0) g_bsum[blockIdx.x] = t;
    }
}

__global__ void scan_boff_kernel() {
    int lane = threadIdx.x;
    int v = (lane < NCHUNK) ? g_bsum[lane] : 0;
    int incl = v;
#pragma unroll
    for (int off = 1; off < 32; off <<= 1) {
        int t = __shfl_up_sync(0xFFFFFFFFu, incl, off);
        if (lane >= off) incl += t;
    }
    if (lane < NCHUNK) g_boff[lane] = incl - v;
    if (lane == NCHUNK - 1) g_start[NNODES] = incl;
}

__global__ void scan_write_kernel() {
    const int tid  = threadIdx.x;
    const int lane = tid & 31;
    const int warp = tid >> 5;
    __shared__ int s_wsum[32];

    int i0 = blockIdx.x * 4096 + tid * 4;
    int4 c = *reinterpret_cast<const int4*>(&g_count[i0]);
    int s0 = c.x, s1 = s0 + c.y, s2 = s1 + c.z, s3 = s2 + c.w;
    int tsum = s3;

    int incl = tsum;
#pragma unroll
    for (int off = 1; off < 32; off <<= 1) {
        int v = __shfl_up_sync(0xFFFFFFFFu, incl, off);
        if (lane >= off) incl += v;
    }
    if (lane == 31) s_wsum[warp] = incl;
    __syncthreads();
    if (warp == 0) {
        int wi = s_wsum[lane];
#pragma unroll
        for (int off = 1; off < 32; off <<= 1) {
            int t = __shfl_up_sync(0xFFFFFFFFu, wi, off);
            if (lane >= off) wi += t;
        }
        s_wsum[lane] = wi;
    }
    __syncthreads();
    int warp_excl = (warp == 0) ? 0 : s_wsum[warp - 1];
    int tbase = g_boff[blockIdx.x] + warp_excl + (incl - tsum);

    int e0 = tbase, e1 = tbase + s0, e2 = tbase + s1, e3 = tbase + s2;
    if (i0 + 0 < NNODES) { g_start[i0 + 0] = e0; g_cursor[i0 + 0] = e0; }
    if (i0 + 1 < NNODES) { g_start[i0 + 1] = e1; g_cursor[i0 + 1] = e1; }
    if (i0 + 2 < NNODES) { g_start[i0 + 2] = e2; g_cursor[i0 + 2] = e2; }
    if (i0 + 3 < NNODES) { g_start[i0 + 3] = e3; g_cursor[i0 + 3] = e3; }
}

__global__ void fill_kernel(const void* __restrict__ idx, int E) {
    int e = blockIdx.x * blockDim.x + threadIdx.x;
    if (e >= E) return;
    long long n = load_node(idx, e, g_idx_is64);
    if ((unsigned long long)n >= (unsigned long long)NNODES) return;
    int pos = atomicAdd(&g_cursor[(int)n], 1);
    if (pos < E_MAX) g_list[pos] = e;
}

// ---------------------------------------------------------------------------
// Gather: one warp per node (grid-stride), 2-edge unrolled (R13 WIN state —
// wider front-batching measured WORSE via L1tex-queue spread; do not touch)
// ---------------------------------------------------------------------------
__global__ void gather_kernel(const float* __restrict__ x,
                              const float* __restrict__ rbf,
                              const float* __restrict__ Wrbf) {
    const int lane = threadIdx.x & 31;
    const int gwarp  = (blockIdx.x * blockDim.x + threadIdx.x) >> 5;
    const int nwarps = (gridDim.x * blockDim.x) >> 5;
    const int h0 = lane * 4;

    float w[4][NRAD];
#pragma unroll
    for (int j = 0; j < 4; j++)
#pragma unroll
        for (int r = 0; r < NRAD; r++)
            w[j][r] = __ldg(&Wrbf[(h0 + j) * NRAD + r]);

    for (int n = gwarp; n < NNODES; n += nwarps) {
        const int p0 = __ldg(&g_start[n]);
        const int p1 = __ldg(&g_start[n + 1]);
        float a0 = 0.f, a1 = 0.f, a2 = 0.f, a3 = 0.f;

        int p = p0;
        for (; p + 2 <= p1; p += 2) {
            int e0 = __ldg(&g_list[p]);
            int e1 = __ldg(&g_list[p + 1]);
            const float2* q0 = reinterpret_cast<const float2*>(rbf + (size_t)e0 * NRAD);
            const float2* q1 = reinterpret_cast<const float2*>(rbf + (size_t)e1 * NRAD);
            float2 ra0 = __ldg(q0 + 0), rb0 = __ldg(q0 + 1), rc0 = __ldg(q0 + 2);
            float2 ra1 = __ldg(q1 + 0), rb1 = __ldg(q1 + 1), rc1 = __ldg(q1 + 2);
            float4 xv0 = *reinterpret_cast<const float4*>(x + (size_t)e0 * HID + h0);
            float4 xv1 = *reinterpret_cast<const float4*>(x + (size_t)e1 * HID + h0);

            float g00 = w[0][0]*ra0.x + w[0][1]*ra0.y + w[0][2]*rb0.x + w[0][3]*rb0.y + w[0][4]*rc0.x + w[0][5]*rc0.y;
            float g01 = w[1][0]*ra0.x + w[1][1]*ra0.y + w[1][2]*rb0.x + w[1][3]*rb0.y + w[1][4]*rc0.x + w[1][5]*rc0.y;
            float g02 = w[2][0]*ra0.x + w[2][1]*ra0.y + w[2][2]*rb0.x + w[2][3]*rb0.y + w[2][4]*rc0.x + w[2][5]*rc0.y;
            float g03 = w[3][0]*ra0.x + w[3][1]*ra0.y + w[3][2]*rb0.x + w[3][3]*rb0.y + w[3][4]*rc0.x + w[3][5]*rc0.y;
            a0 += g00 * xv0.x;  a1 += g01 * xv0.y;  a2 += g02 * xv0.z;  a3 += g03 * xv0.w;

            float g10 = w[0][0]*ra1.x + w[0][1]*ra1.y + w[0][2]*rb1.x + w[0][3]*rb1.y + w[0][4]*rc1.x + w[0][5]*rc1.y;
            float g11 = w[1][0]*ra1.x + w[1][1]*ra1.y + w[1][2]*rb1.x + w[1][3]*rb1.y + w[1][4]*rc1.x + w[1][5]*rc1.y;
            float g12 = w[2][0]*ra1.x + w[2][1]*ra1.y + w[2][2]*rb1.x + w[2][3]*rb1.y + w[2][4]*rc1.x + w[2][5]*rc1.y;
            float g13 = w[3][0]*ra1.x + w[3][1]*ra1.y + w[3][2]*rb1.x + w[3][3]*rb1.y + w[3][4]*rc1.x + w[3][5]*rc1.y;
            a0 += g10 * xv1.x;  a1 += g11 * xv1.y;  a2 += g12 * xv1.z;  a3 += g13 * xv1.w;
        }
        if (p < p1) {
            int e = __ldg(&g_list[p]);
            const float2* q = reinterpret_cast<const float2*>(rbf + (size_t)e * NRAD);
            float2 ra = __ldg(q + 0), rb = __ldg(q + 1), rc = __ldg(q + 2);
            float4 xv = *reinterpret_cast<const float4*>(x + (size_t)e * HID + h0);
            float g0 = w[0][0]*ra.x + w[0][1]*ra.y + w[0][2]*rb.x + w[0][3]*rb.y + w[0][4]*rc.x + w[0][5]*rc.y;
            float g1 = w[1][0]*ra.x + w[1][1]*ra.y + w[1][2]*rb.x + w[1][3]*rb.y + w[1][4]*rc.x + w[1][5]*rc.y;
            float g2 = w[2][0]*ra.x + w[2][1]*ra.y + w[2][2]*rb.x + w[2][3]*rb.y + w[2][4]*rc.x + w[2][5]*rc.y;
            float g3 = w[3][0]*ra.x + w[3][1]*ra.y + w[3][2]*rb.x + w[3][3]*rb.y + w[3][4]*rc.x + w[3][5]*rc.y;
            a0 += g0 * xv.x;  a1 += g1 * xv.y;  a2 += g2 * xv.z;  a3 += g3 * xv.w;
        }
        *reinterpret_cast<float4*>(g_node + (size_t)n * HID + h0) =
            make_float4(a0, a1, a2, a3);
    }
}

// ===========================================================================
// Phase 2: fused 4-layer MLP (R15 WIN base: 64-row CTAs, 2 CTAs/SM,
// cp.async staging). Only change: dual accumulators — acc1 = hi*hi,
// acc2 = hi*lo + lo*hi — doubling independent HMMA chains; summed at epilogue.
// ===========================================================================

__device__ __forceinline__ void mma16816(float* acc,
                                         uint32_t a0, uint32_t a1, uint32_t a2, uint32_t a3,
                                         uint32_t b0, uint32_t b1) {
    asm volatile(
        "mma.sync.aligned.m16n8k16.row.col.f32.bf16.bf16.f32 "
        "{%0,%1,%2,%3}, {%4,%5,%6,%7}, {%8,%9}, {%0,%1,%2,%3};"
        : "+f"(acc[0]), "+f"(acc[1]), "+f"(acc[2]), "+f"(acc[3])
        : "r"(a0), "r"(a1), "r"(a2), "r"(a3), "r"(b0), "r"(b1));
}

__device__ __forceinline__ void cp16(uint32_t smem_addr, const void* gptr) {
    asm volatile("cp.async.cg.shared.global [%0], [%1], 16;"
                 :: "r"(smem_addr), "l"(gptr) : "memory");
}

__global__ void __launch_bounds__(256, 2) mlp_mma_kernel(
    const float* __restrict__ b1, const float* __restrict__ b2,
    const float* __restrict__ b3,
    float* __restrict__ out, int nrows)
{
    extern __shared__ __align__(16) uint32_t sw[];
    uint32_t* s_w = sw;            // combined weight tile [128][LDW4]
    uint32_t* s_a = sw + TILE4;    // combined activation tile [64][LDW4]

    const int tid  = threadIdx.x;
    const int lane = tid & 31;
    const int wid  = tid >> 5;                 // 0..7
    const int qr   = lane >> 2;
    const int qc   = lane & 3;
    const int row0 = blockIdx.x * MROWS;
    const int rloc = (wid & 3) * 16;           // 4 row groups
    const int nh   = wid >> 2;                 // 2 col halves
    const int mAl  = rloc + qr;                // 0..63
    const int mBl  = mAl + 8;
    const int mA   = row0 + mAl;
    const int mB   = row0 + mBl;

    const uint32_t s_w_u32 = (uint32_t)__cvta_generic_to_shared(s_w);

    // ---- Stage layer-0 activations into combined fragment groups ----
    for (int q = tid; q < MROWS * 64; q += 256) {
        int r = q >> 6;
        int w = q & 63;
        float2 v = make_float2(0.f, 0.f);
        if (row0 + r < nrows)
            v = *reinterpret_cast<const float2*>(g_node + (size_t)(row0 + r) * HID + 2 * w);
        uint32_t hi, lo;
        split2(v.x, v.y, hi, lo);
        int slot;
        int base = r * LDW4 + frag_pos(w, slot);
        s_a[base + slot]     = hi;
        s_a[base + 2 + slot] = lo;
    }

    const float* Bs[3] = {b1, b2, b3};

    for (int layer = 0; layer < 4; layer++) {
        // ---- Stage weights via cp.async ----
        {
            const uint4* src = reinterpret_cast<const uint4*>(g_wsplit[layer]);
            for (int q = tid; q < TILE4 / 4; q += 256)
                cp16(s_w_u32 + q * 16, src + q);
            asm volatile("cp.async.commit_group;" ::: "memory");
            asm volatile("cp.async.wait_group 0;" ::: "memory");
        }
        __syncthreads();

        float acc1[8][4], acc2[8][4];
#pragma unroll
        for (int t = 0; t < 8; t++)
#pragma unroll
            for (int j = 0; j < 4; j++) { acc1[t][j] = 0.f; acc2[t][j] = 0.f; }

#pragma unroll
        for (int s = 0; s < 8; s++) {
            int go = 16 * s + 4 * qc;
            uint4 a0 = *reinterpret_cast<const uint4*>(&s_a[mAl * LDW4 + go]);
            uint4 a1 = *reinterpret_cast<const uint4*>(&s_a[mBl * LDW4 + go]);

            // prefetch B for t=0
            int bbase = (nh * 64 + qr) * LDW4 + go;
            uint4 b = *reinterpret_cast<const uint4*>(&s_w[bbase]);

#pragma unroll
            for (int t = 0; t < 8; t++) {
                uint4 cb = b;
                if (t < 7)
                    b = *reinterpret_cast<const uint4*>(&s_w[bbase + (t + 1) * 8 * LDW4]);
                mma16816(acc1[t], a0.x, a1.x, a0.y, a1.y, cb.x, cb.y);   // hi*hi
                mma16816(acc2[t], a0.x, a1.x, a0.y, a1.y, cb.z, cb.w);   // hi*lo
                mma16816(acc2[t], a0.z, a1.z, a0.w, a1.w, cb.x, cb.y);   // lo*hi
            }
        }
        __syncthreads();   // mainloop reads done before epilogue writes s_a / restage s_w

        if (layer < 3) {
            const float* bias = Bs[layer];
#pragma unroll
            for (int t = 0; t < 8; t++) {
                int c0 = nh * 64 + 8 * t + 2 * qc;
                float bb0 = __ldg(&bias[c0]);
                float bb1 = __ldg(&bias[c0 + 1]);
                float v0 = acc1[t][0] + acc2[t][0] + bb0;
                float v1 = acc1[t][1] + acc2[t][1] + bb1;
                float v2 = acc1[t][2] + acc2[t][2] + bb0;
                float v3 = acc1[t][3] + acc2[t][3] + bb1;
                v0 = v0 / (1.f + __expf(-v0));
                v1 = v1 / (1.f + __expf(-v1));
                v2 = v2 / (1.f + __expf(-v2));
                v3 = v3 / (1.f + __expf(-v3));
                uint32_t hA, lA, hB, lB;
                split2(v0, v1, hA, lA);
                split2(v2, v3, hB, lB);
                int w = nh * 32 + 4 * t + qc;
                int slot;
                int gp = frag_pos(w, slot);
                s_a[mAl * LDW4 + gp + slot]     = hA;
                s_a[mAl * LDW4 + gp + 2 + slot] = lA;
                s_a[mBl * LDW4 + gp + slot]     = hB;
                s_a[mBl * LDW4 + gp + 2 + slot] = lB;
            }
            // next iteration's post-staging __syncthreads orders these writes
        } else {
#pragma unroll
            for (int t = 0; t < 8; t++) {
                int c0 = nh * 64 + 8 * t + 2 * qc;
                if (mA < nrows)
                    *reinterpret_cast<float2*>(out + (size_t)mA * HID + c0) =
                        make_float2(acc1[t][0] + acc2[t][0], acc1[t][1] + acc2[t][1]);
                if (mB < nrows)
                    *reinterpret_cast<float2*>(out + (size_t)mB * HID + c0) =
                        make_float2(acc1[t][2] + acc2[t][2], acc1[t][3] + acc2[t][3]);
            }
        }
    }
}

// ---------------------------------------------------------------------------
// Launch
// ---------------------------------------------------------------------------
extern "C" void kernel_launch(void* const* d_in, const int* in_sizes, int n_in,
                              void* d_out, int out_size) {
    const float* x    = (const float*)d_in[0];
    const float* rbf  = (const float*)d_in[1];
    const void*  idx  = d_in[2];
    const float* Wrbf = (const float*)d_in[3];
    const float* W1   = (const float*)d_in[4];
    const float* b1   = (const float*)d_in[5];
    const float* W2   = (const float*)d_in[6];
    const float* b2   = (const float*)d_in[7];
    const float* W3   = (const float*)d_in[8];
    const float* b3   = (const float*)d_in[9];
    const float* Wout = (const float*)d_in[10];

    const int E     = in_sizes[0] / HID;
    const int nrows = out_size / HID;

    detect_idx_kernel<<<1, 32>>>((const int*)idx);
    prep_weights_kernel<<<(4 * 128 * 64 + 255) / 256, 256>>>(W1, W2, W3, Wout);
    zero_count_kernel<<<(NNODES_PAD + 255) / 256, 256>>>();
    hist_kernel<<<(E + 255) / 256, 256>>>(idx, E);
    scan_bsum_kernel<<<NCHUNK, 1024>>>();
    scan_boff_kernel<<<1, 32>>>();
    scan_write_kernel<<<NCHUNK, 1024>>>();
    fill_kernel<<<(E + 255) / 256, 256>>>(idx, E);
    gather_kernel<<<1184, 256>>>(x, rbf, Wrbf);

    const int smem = (TILE4 + ATILE) * 4;   // 110592 B -> 2 CTAs/SM
    cudaFuncSetAttribute(mlp_mma_kernel, cudaFuncAttributeMaxDynamicSharedMemorySize, smem);
    mlp_mma_kernel<<<(nrows + MROWS - 1) / MROWS, 256, smem>>>(
        b1, b2, b3, (float*)d_out, nrows);
}